// round 17
// baseline (speedup 1.0000x reference)
#include <cuda_runtime.h>
#include <stdint.h>

#define BB 4
#define SS 2048
#define DD 1024
#define EE 64
#define CC 64
#define ROWS (BB*SS)          // 8192
#define NOISE_SCALE (1.0f/64.0f)
#define HALF ((size_t)BB*SS*EE*CC)      // elements per output array

// gemm grid: 128 row-tiles x 2 expert-halves
#define EHALF 32

// Dynamic smem: 3-stage pipeline, A 64x68, W 64x32
#define AS_STRIDE 68
#define A_BUF_FLOATS (64*AS_STRIDE)     // 4352
#define W_BUF_FLOATS (64*EHALF)         // 2048
#define AS_FLOATS (3*A_BUF_FLOATS)      // 13056
#define WS_FLOATS (3*W_BUF_FLOATS)      // 6144
#define SMEM_BYTES ((AS_FLOATS + WS_FLOATS)*4)   // 76800 -> 2 blocks/SM

// Scratch: raw logits [row][e] (2MB) + gates transposed [b][e][s] (2MB)
__device__ float g_logits[(size_t)ROWS*EE];
__device__ float g_gatesT[(size_t)BB*EE*SS];

__device__ __forceinline__ void cp_async16(uint32_t dst_smem, const void* src) {
    asm volatile("cp.async.cg.shared.global [%0], [%1], 16;" :: "r"(dst_smem), "l"(src));
}

__device__ __forceinline__ float2 ffma2(float2 a, float2 b, float2 c) {
    unsigned long long au = *reinterpret_cast<unsigned long long*>(&a);
    unsigned long long bu = *reinterpret_cast<unsigned long long*>(&b);
    unsigned long long cu = *reinterpret_cast<unsigned long long*>(&c);
    unsigned long long du;
    asm("fma.rn.f32x2 %0, %1, %2, %3;" : "=l"(du) : "l"(au), "l"(bu), "l"(cu));
    return *reinterpret_cast<float2*>(&du);
}

// ---------------------------------------------------------------------------
// Kernel 1: GEMM -> raw logits. 256 blocks (128 row-tiles x 2 expert-halves)
// x 256 threads; per-block tile 64 rows x 32 experts; thread tile 4 rows x
// 2 experts. 3-stage cp.async pipeline. B operands are contiguous expert
// pairs -> direct LDS.64 FFMA2 operands (no packing). Each (row,e) output is
// fully accumulated in ONE block, k-ascending, single lane -> bit-identical
// to the reference ranking. 2 blocks/SM -> 16 warps for latency hiding.
// ---------------------------------------------------------------------------
__global__ __launch_bounds__(256)
void gemm_kernel(const float* __restrict__ X,
                 const float* __restrict__ W)
{
    extern __shared__ float smem[];
    float* sA = smem;               // [3][64][AS_STRIDE]
    float* sW = smem + AS_FLOATS;   // [3][64][EHALF]

    const int tid   = threadIdx.x;
    const int tx    = tid & 15;     // expert pair: e = ebase + tx*2 {,+1}
    const int ty    = tid >> 4;     // row quad: rows ty*4 .. ty*4+3
    const int rt    = blockIdx.x >> 1;
    const int ebase = (blockIdx.x & 1) * EHALF;
    const int row0  = rt * 64;

    uint32_t smem_u32 = (uint32_t)__cvta_generic_to_shared(smem);
    const uint32_t a_base = smem_u32;
    const uint32_t w_base = smem_u32 + AS_FLOATS * 4;

    // A tile loads: 1024 float4, 4 per thread.
    const int lr  = tid >> 4;       // 0..15
    const int lc  = (tid & 15) * 4; // 0..60
    // W tile loads: 64 rows x 8 float4 = 512 float4, 2 per thread.
    const int wkr = tid >> 2;       // 0..63 (k row)
    const int wc  = tid & 3;        // float4 index 0..3 (+4 for second)

    // Preload tiles 0 and 1.
#pragma unroll
    for (int pre = 0; pre < 2; pre++) {
        const int k0 = pre * 64;
        const uint32_t a_off = a_base + (uint32_t)(pre * A_BUF_FLOATS * 4);
        const uint32_t w_off = w_base + (uint32_t)(pre * W_BUF_FLOATS * 4);
#pragma unroll
        for (int p = 0; p < 4; p++) {
            int r = lr + p * 16;
            cp_async16(a_off + (uint32_t)((r * AS_STRIDE + lc) * 4),
                       &X[(size_t)(row0 + r) * DD + k0 + lc]);
        }
#pragma unroll
        for (int p = 0; p < 2; p++) {
            int c4 = wc + p * 4;    // 0..7
            cp_async16(w_off + (uint32_t)((wkr * EHALF + c4 * 4) * 4),
                       &W[(size_t)(k0 + wkr) * EE + ebase + c4 * 4]);
        }
        asm volatile("cp.async.commit_group;");
    }

    float2 acc[4];
#pragma unroll
    for (int i = 0; i < 4; i++) acc[i] = make_float2(0.f, 0.f);

    for (int it = 0; it < 16; it++) {
        const int buf = it % 3;

        asm volatile("cp.async.wait_group 1;");
        __syncthreads();

        if (it < 14) {
            const int k1 = (it + 2) * 64;
            const int nb = (it + 2) % 3;
            const uint32_t a_off = a_base + (uint32_t)(nb * A_BUF_FLOATS * 4);
            const uint32_t w_off = w_base + (uint32_t)(nb * W_BUF_FLOATS * 4);
#pragma unroll
            for (int p = 0; p < 4; p++) {
                int r = lr + p * 16;
                cp_async16(a_off + (uint32_t)((r * AS_STRIDE + lc) * 4),
                           &X[(size_t)(row0 + r) * DD + k1 + lc]);
            }
#pragma unroll
            for (int p = 0; p < 2; p++) {
                int c4 = wc + p * 4;
                cp_async16(w_off + (uint32_t)((wkr * EHALF + c4 * 4) * 4),
                           &W[(size_t)(k1 + wkr) * EE + ebase + c4 * 4]);
            }
            asm volatile("cp.async.commit_group;");
        } else {
            asm volatile("cp.async.commit_group;");
        }

        const float* A  = sA + buf * A_BUF_FLOATS;
        const float* Bm = sW + buf * W_BUF_FLOATS;
#pragma unroll
        for (int kk = 0; kk < 64; kk += 2) {
            // B: contiguous expert pair -> direct FFMA2 operands.
            float2 b0 = *(const float2*)&Bm[(kk + 0) * EHALF + tx * 2];
            float2 b1 = *(const float2*)&Bm[(kk + 1) * EHALF + tx * 2];
            float2 av[4];
#pragma unroll
            for (int i = 0; i < 4; i++)
                av[i] = *(const float2*)&A[(ty * 4 + i) * AS_STRIDE + kk];
            // k = kk for all rows, then k = kk+1 (per-acc k-ascending).
#pragma unroll
            for (int i = 0; i < 4; i++) {
                float2 axx = make_float2(av[i].x, av[i].x);
                acc[i] = ffma2(axx, b0, acc[i]);
            }
#pragma unroll
            for (int i = 0; i < 4; i++) {
                float2 ayy = make_float2(av[i].y, av[i].y);
                acc[i] = ffma2(ayy, b1, acc[i]);
            }
        }
    }

    // Write raw logits (float2 per row, coalesced across tx).
#pragma unroll
    for (int i = 0; i < 4; i++) {
        int row = row0 + ty * 4 + i;
        *(float2*)&g_logits[(size_t)row * EE + ebase + tx * 2] = acc[i];
    }
}

// ---------------------------------------------------------------------------
// Kernel 2: noise + softmax -> transposed gates. One thread per row.
// l[e] = logits + noise*NOISE_SCALE (same FFMA expression as the previous
// fused epilogue), then max/exp/sum in e-ascending order -> bit-identical.
// ---------------------------------------------------------------------------
__global__ __launch_bounds__(128)
void softmax_kernel(const float* __restrict__ noise)
{
    const int row = blockIdx.x * 128 + threadIdx.x;
    const int b = row / SS;
    const int s = row % SS;

    float l[EE];
    const float4* lg = (const float4*)&g_logits[(size_t)row * EE];
    const float4* nz = (const float4*)&noise[(size_t)row * EE];
#pragma unroll
    for (int i = 0; i < 16; i++) {
        float4 a = lg[i];
        float4 n = nz[i];
        l[4 * i + 0] = a.x + n.x * NOISE_SCALE;
        l[4 * i + 1] = a.y + n.y * NOISE_SCALE;
        l[4 * i + 2] = a.z + n.z * NOISE_SCALE;
        l[4 * i + 3] = a.w + n.w * NOISE_SCALE;
    }

    float m = -1e30f;
#pragma unroll
    for (int e = 0; e < EE; e++) m = fmaxf(m, l[e]);
    float sum = 0.0f;
#pragma unroll
    for (int e = 0; e < EE; e++) {
        float t = expf(l[e] - m);
        l[e] = t;
        sum += t;
    }
    float inv = 1.0f / sum;
#pragma unroll
    for (int e = 0; e < EE; e++)
        g_gatesT[((size_t)b * EE + e) * SS + s] = l[e] * inv;
}

// ---------------------------------------------------------------------------
// Kernel 3: register-resident top-64 (unchanged from R13/R14/R16 wins).
// ---------------------------------------------------------------------------
__global__ __launch_bounds__(512)
void topk_kernel(float* __restrict__ mask_out,
                 float* __restrict__ comb_out)
{
    __shared__ unsigned long long cand[512];
    __shared__ int hist[256];
    __shared__ int warpsum[8], woff[8];
    __shared__ unsigned long long s_prefix, s_thresh;
    __shared__ int s_need, s_done, s_cnt;

    const int tid  = threadIdx.x;
    const int lane = tid & 31;
    const int wrp  = tid >> 5;
    const int b = blockIdx.x >> 6;
    const int e = blockIdx.x & 63;

    unsigned long long k[4];
    const float* col = &g_gatesT[((size_t)b * EE + e) * SS];
#pragma unroll
    for (int j = 0; j < 4; j++) {
        int i = tid + j * 512;
        unsigned int fb = __float_as_uint(col[i]);   // softmax gates > 0
        k[j] = ((unsigned long long)fb << 32) | (unsigned int)(~i);
    }
    if (tid == 0) { s_done = 0; s_need = CC; s_prefix = 0ULL; }
    __syncthreads();

    for (int shift = 56; shift >= 0; shift -= 8) {
        if (s_done) break;
        const unsigned long long pf = s_prefix;
        const int need = s_need;
        if (tid < 256) hist[tid] = 0;
        __syncthreads();
#pragma unroll
        for (int j = 0; j < 4; j++) {
            bool active = (shift == 56) || ((k[j] >> (shift + 8)) == pf);
            if (active) atomicAdd(&hist[(int)((k[j] >> shift) & 255)], 1);
        }
        __syncthreads();

        int own = 0, sfx = 0;
        if (tid < 256) {
            own = hist[tid];
            int v = own;
#pragma unroll
            for (int off = 1; off < 32; off <<= 1) {
                int t = __shfl_down_sync(0xFFFFFFFFu, v, off);
                if (lane + off < 32) v += t;
            }
            if (lane == 0) warpsum[wrp] = v;
            sfx = v;
        }
        __syncthreads();
        if (tid < 8) {
            int acc = 0;
            for (int w = 7; w > tid; w--) acc += warpsum[w];
            woff[tid] = acc;
        }
        __syncthreads();

        if (tid < 256) {
            int c     = sfx + woff[wrp];
            int above = c - own;
            if (c >= need && above < need) {
                int got = (CC - need) + c;
                unsigned long long np = (pf << 8) | (unsigned long long)tid;
                if (got <= 512 || shift == 0) {
                    s_thresh = np << shift;
                    s_done = 1;
                } else {
                    s_need = need - above;
                    s_prefix = np;
                }
            }
        }
        __syncthreads();
    }

    cand[tid] = 0ULL;
    if (tid == 0) s_cnt = 0;
    __syncthreads();
    {
        const unsigned long long T = s_thresh;
#pragma unroll
        for (int j = 0; j < 4; j++) {
            if (k[j] >= T) {
                int p = atomicAdd(&s_cnt, 1);
                if (p < 512) cand[p] = k[j];
            }
        }
    }
    __syncthreads();

    int cnt = s_cnt;
    int nsort = 64;
    while (nsort < cnt && nsort < 512) nsort <<= 1;

    for (int k2 = 2; k2 <= nsort; k2 <<= 1) {
        for (int j = k2 >> 1; j > 0; j >>= 1) {
            if (tid < (nsort >> 1)) {
                int i   = ((tid & ~(j - 1)) << 1) | (tid & (j - 1));
                int ixj = i | j;
                bool desc = ((i & k2) == 0);
                unsigned long long a = cand[i];
                unsigned long long c = cand[ixj];
                if ((a < c) == desc) { cand[i] = c; cand[ixj] = a; }
            }
            __syncthreads();
        }
    }

    if (tid < CC) {
        unsigned long long kk = cand[tid];
        int   s = (int)(~(unsigned int)kk);
        float v = __uint_as_float((unsigned int)(kk >> 32));
        size_t idx = ((((size_t)b * SS + s) * EE + e) << 6) + tid;
        mask_out[idx] = 1.0f;
        comb_out[idx] = v;
    }
}

// ---------------------------------------------------------------------------
// STRICTLY SERIAL pipeline: memset -> gemm -> softmax -> topk.
// ---------------------------------------------------------------------------
extern "C" void kernel_launch(void* const* d_in, const int* in_sizes, int n_in,
                              void* d_out, int out_size)
{
    const float* X     = (const float*)d_in[0];   // [B,S,D]
    const float* W     = (const float*)d_in[1];   // [D,E]
    const float* noise = (const float*)d_in[2];   // [B,S,E]
    float* out = (float*)d_out;

    cudaFuncSetAttribute(gemm_kernel,
                         cudaFuncAttributeMaxDynamicSharedMemorySize, SMEM_BYTES);

    cudaMemsetAsync(out, 0, (size_t)out_size * sizeof(float), 0);
    gemm_kernel<<<256, 256, SMEM_BYTES>>>(X, W);
    softmax_kernel<<<ROWS / 128, 128>>>(noise);
    topk_kernel<<<BB * EE, 512>>>(out, out + HALF);
}